// round 1
// baseline (speedup 1.0000x reference)
#include <cuda_runtime.h>
#include <cstdint>
#include <cstddef>

// ---------------------------------------------------------------------------
// Problem constants
// ---------------------------------------------------------------------------
#define S_  97
#define B_  256
#define W_  1024
#define H_  16
#define HD_ 64
#define M_  (S_ * B_)      // 24832 = 194 * 128
#define KDIM 1024          // inner dim of every GEMM
#define NDIM 1024          // output dim of every GEMM

// GEMM tiling
#define BM 128
#define BN 128
#define BK 32
#define PAD 36             // smem row stride in floats (conflict-free + 16B aligned)
#define STAGE_FLOATS (BM * PAD + BN * PAD)     // 9216 floats per stage
#define GEMM_SMEM_BYTES (2 * STAGE_FLOATS * 4) // 73728 B (double buffered)

// Attention smem
#define APAD 65
#define ATTN_SMEM_FLOATS (3 * 97 * APAD + 8 * 4 * 97)  // Q,K,V tiles + P buffer
#define ATTN_SMEM_BYTES (ATTN_SMEM_FLOATS * 4)         // 88076 B

// ---------------------------------------------------------------------------
// Scratch (static device globals: no allocation allowed)
// ---------------------------------------------------------------------------
__device__ float g_b0[M_ * (size_t)W_];   // q1 / later O
__device__ float g_b1[M_ * (size_t)W_];   // k1 / later T1
__device__ float g_b2[M_ * (size_t)W_];   // v1
__device__ float g_b3[M_ * (size_t)W_];   // q2
__device__ float g_b4[M_ * (size_t)W_];   // k2
__device__ float g_b5[M_ * (size_t)W_];   // v2
__device__ float g_cos[S_ * 512];
__device__ float g_sin[S_ * 512];

// ---------------------------------------------------------------------------
// Helpers
// ---------------------------------------------------------------------------
__device__ __forceinline__ uint32_t f2tf(float f) {
    uint32_t u;
    asm("cvt.rna.tf32.f32 %0, %1;" : "=r"(u) : "f"(f));
    return u;
}

__device__ __forceinline__ void mma_tf32(float* c, const uint32_t* a, const uint32_t* b) {
    asm volatile(
        "mma.sync.aligned.m16n8k8.row.col.f32.tf32.tf32.f32 "
        "{%0,%1,%2,%3},{%4,%5,%6,%7},{%8,%9},{%0,%1,%2,%3};"
        : "+f"(c[0]), "+f"(c[1]), "+f"(c[2]), "+f"(c[3])
        : "r"(a[0]), "r"(a[1]), "r"(a[2]), "r"(a[3]), "r"(b[0]), "r"(b[1]));
}

// ---------------------------------------------------------------------------
// RoPE table precompute: cos/sin of s * 10000^(-p/512) for s in [0,97), p in [0,512)
// ---------------------------------------------------------------------------
__global__ void rope_tab_kernel(float* __restrict__ ct, float* __restrict__ st) {
    int i = blockIdx.x * 256 + threadIdx.x;
    if (i >= S_ * 512) return;
    int s = i / 512, p = i % 512;
    float inv = powf(10000.0f, -(float)p * (1.0f / 512.0f));
    float ang = (float)s * inv;
    ct[i] = cosf(ang);
    st[i] = sinf(ang);
}

// ---------------------------------------------------------------------------
// GEMM: C[M, 1024] = A[M, 1024] @ Wm[1024, 1024]^T + bias, optional fused RoPE.
// Wm is row-major (N, K); mma wants B[k][n] = Wm[n][k], loaded straight.
// Exact tiling: M = 194*128, N = 8*128, K = 32*32. No bounds checks.
// ---------------------------------------------------------------------------
__global__ __launch_bounds__(256, 2)
void gemm_kernel(const float* __restrict__ A, const float* __restrict__ Wm,
                 const float* __restrict__ bias, float* __restrict__ C,
                 int doRope,
                 const float* __restrict__ cosT, const float* __restrict__ sinT)
{
    extern __shared__ float sm[];
    const int tid  = threadIdx.x;
    const int lane = tid & 31;
    const int warp = tid >> 5;
    const int wr   = warp >> 2;   // 0..1 : warp row (64 M-rows each)
    const int wc   = warp & 3;    // 0..3 : warp col (32 N-cols each)
    const int m0   = blockIdx.y * BM;
    const int n0   = blockIdx.x * BN;

    // per-thread gmem->smem load coords: 4 chunks of 16B for A and for B
    const int row0 = tid >> 3;          // rows row0, row0+32, +64, +96
    const int c4   = (tid & 7) * 4;     // float offset within 32-float row
    const float* Abase = A  + (size_t)(m0 + row0) * KDIM + c4;
    const float* Bbase = Wm + (size_t)(n0 + row0) * KDIM + c4;

    float acc[4][4][4];
    #pragma unroll
    for (int i = 0; i < 4; i++)
        #pragma unroll
        for (int j = 0; j < 4; j++)
            #pragma unroll
            for (int c = 0; c < 4; c++) acc[i][j][c] = 0.0f;

#define LOAD_STAGE(sg, k0)                                                          \
    do {                                                                            \
        float* dA = sm + (sg) * STAGE_FLOATS;                                       \
        float* dB = dA + BM * PAD;                                                  \
        _Pragma("unroll")                                                           \
        for (int i_ = 0; i_ < 4; i_++) {                                            \
            int row_ = row0 + i_ * 32;                                              \
            uint32_t da_ = (uint32_t)__cvta_generic_to_shared(dA + row_ * PAD + c4);\
            asm volatile("cp.async.ca.shared.global [%0], [%1], 16;"                \
                         :: "r"(da_), "l"(Abase + (size_t)i_ * 32 * KDIM + (k0)));  \
            uint32_t db_ = (uint32_t)__cvta_generic_to_shared(dB + row_ * PAD + c4);\
            asm volatile("cp.async.ca.shared.global [%0], [%1], 16;"                \
                         :: "r"(db_), "l"(Bbase + (size_t)i_ * 32 * KDIM + (k0)));  \
        }                                                                           \
        asm volatile("cp.async.commit_group;" ::: "memory");                        \
    } while (0)

#define COMPUTE_STAGE(sg)                                                           \
    do {                                                                            \
        const float* a_   = sm + (sg) * STAGE_FLOATS;                               \
        const float* bsh_ = a_ + BM * PAD;                                          \
        const int r_ = lane >> 2, cc_ = lane & 3;                                   \
        _Pragma("unroll")                                                           \
        for (int ks = 0; ks < 4; ks++) {                                            \
            uint32_t af[4][4], bf[4][2];                                            \
            _Pragma("unroll")                                                       \
            for (int i_ = 0; i_ < 4; i_++) {                                        \
                const float* ap = a_ + (wr * 64 + i_ * 16 + r_) * PAD + ks * 8 + cc_;\
                af[i_][0] = f2tf(ap[0]);                                            \
                af[i_][1] = f2tf(ap[8 * PAD]);                                      \
                af[i_][2] = f2tf(ap[4]);                                            \
                af[i_][3] = f2tf(ap[8 * PAD + 4]);                                  \
            }                                                                       \
            _Pragma("unroll")                                                       \
            for (int j_ = 0; j_ < 4; j_++) {                                        \
                const float* bp = bsh_ + (wc * 32 + j_ * 8 + r_) * PAD + ks * 8 + cc_;\
                bf[j_][0] = f2tf(bp[0]);                                            \
                bf[j_][1] = f2tf(bp[4]);                                            \
            }                                                                       \
            _Pragma("unroll")                                                       \
            for (int i_ = 0; i_ < 4; i_++)                                          \
                _Pragma("unroll")                                                   \
                for (int j_ = 0; j_ < 4; j_++)                                      \
                    mma_tf32(acc[i_][j_], af[i_], bf[j_]);                          \
        }                                                                           \
    } while (0)

    LOAD_STAGE(0, 0);
    #pragma unroll 2
    for (int t = 0; t < KDIM / BK; t++) {
        if (t + 1 < KDIM / BK) {
            LOAD_STAGE((t + 1) & 1, (t + 1) * BK);
            asm volatile("cp.async.wait_group 1;" ::: "memory");
        } else {
            asm volatile("cp.async.wait_group 0;" ::: "memory");
        }
        __syncthreads();
        COMPUTE_STAGE(t & 1);
        __syncthreads();
    }

    // ---- epilogue: bias (+ optional RoPE on even/odd column pairs) ----
    const int r  = lane >> 2;
    const int c2 = (lane & 3) * 2;
    #pragma unroll
    for (int i = 0; i < 4; i++) {
        int grow0 = m0 + wr * 64 + i * 16 + r;
        #pragma unroll
        for (int j = 0; j < 4; j++) {
            int gcol = n0 + wc * 32 + j * 8 + c2;   // always even
            float be = bias[gcol];
            float bo = bias[gcol + 1];
            float v0 = acc[i][j][0] + be;
            float v1 = acc[i][j][1] + bo;
            float v2 = acc[i][j][2] + be;
            float v3 = acc[i][j][3] + bo;
            if (doRope) {
                int p  = gcol >> 1;
                int s0 = grow0 >> 8;          // row / B_ (B_ = 256)
                int s1 = (grow0 + 8) >> 8;
                float ca = cosT[s0 * 512 + p], sa = sinT[s0 * 512 + p];
                float cb = cosT[s1 * 512 + p], sb = sinT[s1 * 512 + p];
                float t0 = v0 * ca - v1 * sa;  v1 = v0 * sa + v1 * ca;  v0 = t0;
                float t2 = v2 * cb - v3 * sb;  v3 = v2 * sb + v3 * cb;  v2 = t2;
            }
            *(float2*)&C[(size_t)grow0 * NDIM + gcol]       = make_float2(v0, v1);
            *(float2*)&C[(size_t)(grow0 + 8) * NDIM + gcol] = make_float2(v2, v3);
        }
    }
#undef LOAD_STAGE
#undef COMPUTE_STAGE
}

// ---------------------------------------------------------------------------
// Attention: one block per (b, h). Q/K/V head tiles (97 x 64 fp32) in smem.
// 8 warps x 4 queries per pass; warp lanes own key indices (lane + 32*kk).
// scores = (Q K^T) * 0.125 + mask ; softmax over keys ; O = P V.
// ---------------------------------------------------------------------------
__global__ __launch_bounds__(256, 2)
void attn_kernel(const float* __restrict__ Q, const float* __restrict__ Kx,
                 const float* __restrict__ V, const float* __restrict__ mask,
                 float* __restrict__ O)
{
    extern __shared__ float sm[];
    float* sQ = sm;
    float* sK = sQ + 97 * APAD;
    float* sV = sK + 97 * APAD;
    float* sP = sV + 97 * APAD;   // [8 warps][4 q][97]

    const int tid  = threadIdx.x;
    const int lane = tid & 31;
    const int warp = tid >> 5;
    const int b = blockIdx.x >> 4;
    const int h = blockIdx.x & 15;
    const size_t base = (size_t)b * W_ + (size_t)h * HD_;
    const size_t srow = (size_t)B_ * W_;

    for (int idx = tid; idx < 97 * 64; idx += 256) {
        int row = idx >> 6, d = idx & 63;
        size_t g = (size_t)row * srow + base + d;
        sQ[row * APAD + d] = Q[g];
        sK[row * APAD + d] = Kx[g];
        sV[row * APAD + d] = V[g];
    }
    __syncthreads();

    for (int qb = 0; qb < 128; qb += 32) {
        int q0 = qb + warp * 4;

        // ---- scores ----
        float sc[4][4];
        #pragma unroll
        for (int qi = 0; qi < 4; qi++)
            #pragma unroll
            for (int kk = 0; kk < 4; kk++) sc[qi][kk] = 0.0f;

        #pragma unroll 4
        for (int d = 0; d < 64; d++) {
            float kv[4];
            #pragma unroll
            for (int kk = 0; kk < 4; kk++) {
                int k = lane + kk * 32;
                kv[kk] = (k < 97) ? sK[k * APAD + d] : 0.0f;
            }
            #pragma unroll
            for (int qi = 0; qi < 4; qi++) {
                int q = q0 + qi;
                float qv = (q < 97) ? sQ[q * APAD + d] : 0.0f;
                #pragma unroll
                for (int kk = 0; kk < 4; kk++)
                    sc[qi][kk] = fmaf(qv, kv[kk], sc[qi][kk]);
            }
        }

        // ---- softmax (per query, across warp lanes) ----
        #pragma unroll
        for (int qi = 0; qi < 4; qi++) {
            int q = q0 + qi;
            float sv[4];
            float mx = -3.0e38f;
            #pragma unroll
            for (int kk = 0; kk < 4; kk++) {
                int k = lane + kk * 32;
                float v = (q < 97 && k < 97) ? sc[qi][kk] * 0.125f + mask[q * S_ + k]
                                             : -3.0e38f;
                sv[kk] = v;
                mx = fmaxf(mx, v);
            }
            for (int o = 16; o > 0; o >>= 1)
                mx = fmaxf(mx, __shfl_xor_sync(0xffffffffu, mx, o));
            float sum = 0.0f;
            #pragma unroll
            for (int kk = 0; kk < 4; kk++) {
                int k = lane + kk * 32;
                float e = (q < 97 && k < 97) ? __expf(sv[kk] - mx) : 0.0f;
                sv[kk] = e;
                sum += e;
            }
            for (int o = 16; o > 0; o >>= 1)
                sum += __shfl_xor_sync(0xffffffffu, sum, o);
            float inv = (q < 97) ? (1.0f / sum) : 0.0f;
            #pragma unroll
            for (int kk = 0; kk < 4; kk++) {
                int k = lane + kk * 32;
                if (k < 97) sP[(warp * 4 + qi) * 97 + k] = sv[kk] * inv;
            }
        }
        __syncwarp();

        // ---- O = P V ----
        #pragma unroll
        for (int dd = 0; dd < 2; dd++) {
            int d = lane + dd * 32;
            float accq[4] = {0.f, 0.f, 0.f, 0.f};
            #pragma unroll 4
            for (int k = 0; k < 97; k++) {
                float vv = sV[k * APAD + d];
                #pragma unroll
                for (int qi = 0; qi < 4; qi++)
                    accq[qi] = fmaf(sP[(warp * 4 + qi) * 97 + k], vv, accq[qi]);
            }
            #pragma unroll
            for (int qi = 0; qi < 4; qi++) {
                int q = q0 + qi;
                if (q < 97) O[(size_t)q * srow + base + d] = accq[qi];
            }
        }
        __syncwarp();
    }
}

// ---------------------------------------------------------------------------
// Host launcher
// ---------------------------------------------------------------------------
extern "C" void kernel_launch(void* const* d_in, const int* in_sizes, int n_in,
                              void* d_out, int out_size)
{
    (void)in_sizes; (void)n_in; (void)out_size;
    const float* tensor = (const float*)d_in[0];
    const float* mask   = (const float*)d_in[1];
    const float* q_w    = (const float*)d_in[2];
    const float* q_b    = (const float*)d_in[3];
    const float* k_w    = (const float*)d_in[4];
    const float* k_b    = (const float*)d_in[5];
    const float* v_w    = (const float*)d_in[6];
    const float* v_b    = (const float*)d_in[7];
    const float* ipw    = (const float*)d_in[8];
    const float* ipb    = (const float*)d_in[9];
    const float* mow    = (const float*)d_in[10];
    const float* mob    = (const float*)d_in[11];
    const float* ow     = (const float*)d_in[12];
    const float* ob     = (const float*)d_in[13];
    float* out = (float*)d_out;

    float *b0, *b1, *b2, *b3, *b4, *b5, *ct, *st;
    cudaGetSymbolAddress((void**)&b0, g_b0);
    cudaGetSymbolAddress((void**)&b1, g_b1);
    cudaGetSymbolAddress((void**)&b2, g_b2);
    cudaGetSymbolAddress((void**)&b3, g_b3);
    cudaGetSymbolAddress((void**)&b4, g_b4);
    cudaGetSymbolAddress((void**)&b5, g_b5);
    cudaGetSymbolAddress((void**)&ct, g_cos);
    cudaGetSymbolAddress((void**)&st, g_sin);

    cudaFuncSetAttribute(gemm_kernel, cudaFuncAttributeMaxDynamicSharedMemorySize,
                         GEMM_SMEM_BYTES);
    cudaFuncSetAttribute(attn_kernel, cudaFuncAttributeMaxDynamicSharedMemorySize,
                         ATTN_SMEM_BYTES);

    rope_tab_kernel<<<(S_ * 512 + 255) / 256, 256>>>(ct, st);

    dim3 gg(NDIM / BN, M_ / BM);   // (8, 194)

    // Stage 1: first projections (+RoPE on q,k)
    gemm_kernel<<<gg, 256, GEMM_SMEM_BYTES>>>(tensor, q_w, q_b, b0, 1, ct, st);
    gemm_kernel<<<gg, 256, GEMM_SMEM_BYTES>>>(tensor, k_w, k_b, b1, 1, ct, st);
    gemm_kernel<<<gg, 256, GEMM_SMEM_BYTES>>>(tensor, v_w, v_b, b2, 0, ct, st);

    // Stage 2: in_proj split projections
    gemm_kernel<<<gg, 256, GEMM_SMEM_BYTES>>>(b0, ipw,                 ipb,        b3, 0, ct, st);
    gemm_kernel<<<gg, 256, GEMM_SMEM_BYTES>>>(b1, ipw + 1024 * 1024,   ipb + 1024, b4, 0, ct, st);
    gemm_kernel<<<gg, 256, GEMM_SMEM_BYTES>>>(b2, ipw + 2 * 1024 * 1024, ipb + 2048, b5, 0, ct, st);

    // Stage 3: attention (O -> b0, reusing q1 buffer)
    attn_kernel<<<B_ * H_, 256, ATTN_SMEM_BYTES>>>(b3, b4, b5, mask, b0);

    // Stage 4: output projections
    gemm_kernel<<<gg, 256, GEMM_SMEM_BYTES>>>(b0, mow, mob, b1, 0, ct, st);
    gemm_kernel<<<gg, 256, GEMM_SMEM_BYTES>>>(b1, ow,  ob,  out, 0, ct, st);
}

// round 4
// speedup vs baseline: 1.1077x; 1.1077x over previous
#include <cuda_runtime.h>
#include <cstdint>
#include <cstddef>

// ---------------------------------------------------------------------------
// Problem constants
// ---------------------------------------------------------------------------
#define S_  97
#define B_  256
#define W_  1024
#define H_  16
#define HD_ 64
#define M_  (S_ * B_)      // 24832 = 194 * 128
#define KDIM 1024
#define NDIM 1024

// GEMM tiling (legacy mma.sync path; tcgen05 unavailable: target is compute_100)
#define BM 128
#define BN 128
#define BK 32
#define PAD 36                               // smem row stride (floats), conflict-free
#define STAGE_FLOATS ((BM + BN) * PAD)       // 9216 floats / stage
#define NSTAGE 3
#define GEMM_SMEM_BYTES (NSTAGE * STAGE_FLOATS * 4)   // 110592 B
#define NITER (KDIM / BK)                    // 32

// flags
#define FLG_ROPE  1
#define FLG_ROUND 2

// Attention smem
#define APAD 68                              // floats per row (17 float4; 4-bank stride)
#define PSTRIDE 100                          // P row stride (k contiguous, 16B aligned)
#define ATTN_SMEM_FLOATS (3 * 97 * APAD + 64 * PSTRIDE)
#define ATTN_SMEM_BYTES (ATTN_SMEM_FLOATS * 4)   // 104752 B

// ---------------------------------------------------------------------------
// Scratch (static device globals: no allocation allowed)
// ---------------------------------------------------------------------------
__device__ float g_b0[M_ * (size_t)W_];
__device__ float g_b1[M_ * (size_t)W_];
__device__ float g_b2[M_ * (size_t)W_];
__device__ float g_b3[M_ * (size_t)W_];
__device__ float g_b4[M_ * (size_t)W_];
__device__ float g_b5[M_ * (size_t)W_];
__device__ float g_t [M_ * (size_t)W_];       // tf32-rounded input tensor
__device__ float g_wr[8u * 1024u * 1024u];    // tf32-rounded weights
__device__ float g_cos[S_ * 512];
__device__ float g_sin[S_ * 512];

// ---------------------------------------------------------------------------
// Helpers
// ---------------------------------------------------------------------------
__device__ __forceinline__ uint32_t f2tf(float f) {    // tf32 round-to-nearest bits
    uint32_t u;
    asm("cvt.rna.tf32.f32 %0, %1;" : "=r"(u) : "f"(f));
    return u;
}
__device__ __forceinline__ float tf32r(float f) { return __uint_as_float(f2tf(f)); }

__device__ __forceinline__ void mma_tf32(float* c, const uint32_t* a, const uint32_t* b) {
    asm volatile(
        "mma.sync.aligned.m16n8k8.row.col.f32.tf32.tf32.f32 "
        "{%0,%1,%2,%3},{%4,%5,%6,%7},{%8,%9},{%0,%1,%2,%3};"
        : "+f"(c[0]), "+f"(c[1]), "+f"(c[2]), "+f"(c[3])
        : "r"(a[0]), "r"(a[1]), "r"(a[2]), "r"(a[3]), "r"(b[0]), "r"(b[1]));
}

__device__ __forceinline__ void cp16(uint32_t s, const void* g) {
    asm volatile("cp.async.cg.shared.global [%0], [%1], 16;" :: "r"(s), "l"(g));
}

// ---------------------------------------------------------------------------
// RoPE table + tf32 pre-round kernels
// ---------------------------------------------------------------------------
__global__ void rope_tab_kernel(float* __restrict__ ct, float* __restrict__ st) {
    int i = blockIdx.x * 256 + threadIdx.x;
    if (i >= S_ * 512) return;
    int s = i / 512, p = i % 512;
    float inv = powf(10000.0f, -(float)p * (1.0f / 512.0f));
    float ang = (float)s * inv;
    ct[i] = cosf(ang);
    st[i] = sinf(ang);
}

__global__ void round_tf32_kernel(const float4* __restrict__ in,
                                  float4* __restrict__ out, int n4) {
    int i = blockIdx.x * 256 + threadIdx.x;
    if (i >= n4) return;
    float4 v = in[i];
    v.x = tf32r(v.x); v.y = tf32r(v.y); v.z = tf32r(v.z); v.w = tf32r(v.w);
    out[i] = v;
}

// ---------------------------------------------------------------------------
// GEMM: C[M,1024] = A[M,1024] @ Wm^T + bias (+RoPE) (+tf32 round of output).
// Inputs MUST be pre-rounded to tf32 values (no cvt in the inner loop).
// 3-stage cp.async pipeline, one __syncthreads per K-iteration.
// ---------------------------------------------------------------------------
__global__ __launch_bounds__(256, 2)
void gemm_kernel(const float* __restrict__ A, const float* __restrict__ Wm,
                 const float* __restrict__ bias, float* __restrict__ C,
                 int flags,
                 const float* __restrict__ cosT, const float* __restrict__ sinT)
{
    extern __shared__ float sm[];
    const int tid  = threadIdx.x;
    const int lane = tid & 31;
    const int warp = tid >> 5;
    const int wr   = warp >> 2;   // 0..1
    const int wc   = warp & 3;    // 0..3
    const int m0   = blockIdx.y * BM;
    const int n0   = blockIdx.x * BN;

    const int row0 = tid >> 3;          // rows row0 + i*32
    const int c4   = (tid & 7) * 4;
    const float* Abase = A  + (size_t)(m0 + row0) * KDIM + c4;
    const float* Bbase = Wm + (size_t)(n0 + row0) * KDIM + c4;

    float acc[4][4][4];
    #pragma unroll
    for (int i = 0; i < 4; i++)
        #pragma unroll
        for (int j = 0; j < 4; j++)
            #pragma unroll
            for (int c = 0; c < 4; c++) acc[i][j][c] = 0.0f;

#define LOAD_STAGE(sg, k0)                                                          \
    do {                                                                            \
        float* dA = sm + (sg) * STAGE_FLOATS;                                       \
        float* dB = dA + BM * PAD;                                                  \
        _Pragma("unroll")                                                           \
        for (int i_ = 0; i_ < 4; i_++) {                                            \
            int row_ = row0 + i_ * 32;                                              \
            uint32_t da_ = (uint32_t)__cvta_generic_to_shared(dA + row_ * PAD + c4);\
            cp16(da_, Abase + (size_t)i_ * 32 * KDIM + (k0));                       \
            uint32_t db_ = (uint32_t)__cvta_generic_to_shared(dB + row_ * PAD + c4);\
            cp16(db_, Bbase + (size_t)i_ * 32 * KDIM + (k0));                       \
        }                                                                           \
        asm volatile("cp.async.commit_group;" ::: "memory");                        \
    } while (0)

#define COMPUTE_STAGE(sg)                                                           \
    do {                                                                            \
        const uint32_t* a_   = (const uint32_t*)(sm + (sg) * STAGE_FLOATS);         \
        const uint32_t* bsh_ = a_ + BM * PAD;                                       \
        const int r_ = lane >> 2, cc_ = lane & 3;                                   \
        _Pragma("unroll")                                                           \
        for (int ks = 0; ks < 4; ks++) {                                            \
            uint32_t af[4][4], bf[4][2];                                            \
            _Pragma("unroll")                                                       \
            for (int i_ = 0; i_ < 4; i_++) {                                        \
                const uint32_t* ap = a_ + (wr * 64 + i_ * 16 + r_) * PAD + ks * 8 + cc_;\
                af[i_][0] = ap[0];                                                  \
                af[i_][1] = ap[8 * PAD];                                            \
                af[i_][2] = ap[4];                                                  \
                af[i_][3] = ap[8 * PAD + 4];                                        \
            }                                                                       \
            _Pragma("unroll")                                                       \
            for (int j_ = 0; j_ < 4; j_++) {                                        \
                const uint32_t* bp = bsh_ + (wc * 32 + j_ * 8 + r_) * PAD + ks * 8 + cc_;\
                bf[j_][0] = bp[0];                                                  \
                bf[j_][1] = bp[4];                                                  \
            }                                                                       \
            _Pragma("unroll")                                                       \
            for (int i_ = 0; i_ < 4; i_++)                                          \
                _Pragma("unroll")                                                   \
                for (int j_ = 0; j_ < 4; j_++)                                      \
                    mma_tf32(acc[i_][j_], af[i_], bf[j_]);                          \
        }                                                                           \
    } while (0)

    LOAD_STAGE(0, 0);
    LOAD_STAGE(1, BK);

    #pragma unroll 1
    for (int t = 0; t < NITER; t++) {
        if (t + 2 < NITER) {
            asm volatile("cp.async.wait_group 1;" ::: "memory");
        } else {
            asm volatile("cp.async.wait_group 0;" ::: "memory");
        }
        __syncthreads();
        if (t + 2 < NITER)
            LOAD_STAGE((t + 2) % NSTAGE, (t + 2) * BK);
        COMPUTE_STAGE(t % NSTAGE);
    }

    // ---- epilogue: bias (+ optional RoPE) (+ optional tf32 rounding) ----
    const int r  = lane >> 2;
    const int c2 = (lane & 3) * 2;
    const int doRope  = flags & FLG_ROPE;
    const int doRound = flags & FLG_ROUND;
    #pragma unroll
    for (int i = 0; i < 4; i++) {
        int grow0 = m0 + wr * 64 + i * 16 + r;
        #pragma unroll
        for (int j = 0; j < 4; j++) {
            int gcol = n0 + wc * 32 + j * 8 + c2;   // always even
            float be = bias[gcol];
            float bo = bias[gcol + 1];
            float v0 = acc[i][j][0] + be;
            float v1 = acc[i][j][1] + bo;
            float v2 = acc[i][j][2] + be;
            float v3 = acc[i][j][3] + bo;
            if (doRope) {
                int p  = gcol >> 1;
                int s0 = grow0 >> 8;          // row / 256
                int s1 = (grow0 + 8) >> 8;
                float ca = cosT[s0 * 512 + p], sa = sinT[s0 * 512 + p];
                float cb = cosT[s1 * 512 + p], sb = sinT[s1 * 512 + p];
                float t0 = v0 * ca - v1 * sa;  v1 = v0 * sa + v1 * ca;  v0 = t0;
                float t2 = v2 * cb - v3 * sb;  v3 = v2 * sb + v3 * cb;  v2 = t2;
            }
            if (doRound) {
                v0 = tf32r(v0); v1 = tf32r(v1); v2 = tf32r(v2); v3 = tf32r(v3);
            }
            *(float2*)&C[(size_t)grow0 * NDIM + gcol]       = make_float2(v0, v1);
            *(float2*)&C[(size_t)(grow0 + 8) * NDIM + gcol] = make_float2(v2, v3);
        }
    }
#undef LOAD_STAGE
#undef COMPUTE_STAGE
}

// ---------------------------------------------------------------------------
// Attention: one block per (b, h). Vectorized float4/float2 smem accesses.
// 8 warps x 8 queries per pass, 2 passes. Output rounded to tf32.
// ---------------------------------------------------------------------------
__global__ __launch_bounds__(256, 2)
void attn_kernel(const float* __restrict__ Q, const float* __restrict__ Kx,
                 const float* __restrict__ V, const float* __restrict__ mask,
                 float* __restrict__ O)
{
    extern __shared__ float sm[];
    float* sQ = sm;
    float* sK = sQ + 97 * APAD;
    float* sV = sK + 97 * APAD;
    float* sP = sV + 97 * APAD;   // [64 rows][PSTRIDE], rows = warp*8 + qi

    const int tid  = threadIdx.x;
    const int lane = tid & 31;
    const int warp = tid >> 5;
    const int b = blockIdx.x >> 4;
    const int h = blockIdx.x & 15;
    const size_t base = (size_t)b * W_ + (size_t)h * HD_;
    const size_t srow = (size_t)B_ * W_;

    // load Q/K/V head tiles as float4
    for (int idx = tid; idx < 97 * 16; idx += 256) {
        int row = idx >> 4, d4 = (idx & 15) * 4;
        const float4* g = (const float4*)(Q + (size_t)row * srow + base + d4);
        *(float4*)&sQ[row * APAD + d4] = *g;
        g = (const float4*)(Kx + (size_t)row * srow + base + d4);
        *(float4*)&sK[row * APAD + d4] = *g;
        g = (const float4*)(V + (size_t)row * srow + base + d4);
        *(float4*)&sV[row * APAD + d4] = *g;
    }
    // zero padding tail of P rows (k = 97..99) once
    for (int idx = tid; idx < 64 * 3; idx += 256)
        sP[(idx / 3) * PSTRIDE + 97 + (idx % 3)] = 0.0f;
    __syncthreads();

    const int kcl[4] = { lane, lane + 32, lane + 64, (lane + 96 < 97) ? lane + 96 : 0 };

    for (int pass = 0; pass < 2; pass++) {
        const int q0 = pass * 64 + warp * 8;

        // ---- scores: sc[qi][kk] = Q[q0+qi] . K[lane + kk*32] ----
        float sc[8][4];
        #pragma unroll
        for (int qi = 0; qi < 8; qi++)
            #pragma unroll
            for (int kk = 0; kk < 4; kk++) sc[qi][kk] = 0.0f;

        #pragma unroll 4
        for (int d4 = 0; d4 < 64; d4 += 4) {
            float4 kv[4];
            #pragma unroll
            for (int kk = 0; kk < 4; kk++)
                kv[kk] = *(const float4*)&sK[kcl[kk] * APAD + d4];
            #pragma unroll
            for (int qi = 0; qi < 8; qi++) {
                int q = q0 + qi; if (q > 96) q = 96;
                float4 qv = *(const float4*)&sQ[q * APAD + d4];
                #pragma unroll
                for (int kk = 0; kk < 4; kk++) {
                    sc[qi][kk] = fmaf(qv.x, kv[kk].x, sc[qi][kk]);
                    sc[qi][kk] = fmaf(qv.y, kv[kk].y, sc[qi][kk]);
                    sc[qi][kk] = fmaf(qv.z, kv[kk].z, sc[qi][kk]);
                    sc[qi][kk] = fmaf(qv.w, kv[kk].w, sc[qi][kk]);
                }
            }
        }

        // ---- softmax per query ----
        #pragma unroll
        for (int qi = 0; qi < 8; qi++) {
            int q = q0 + qi;
            int qc = (q > 96) ? 96 : q;
            float sv[4];
            float mx = -3.0e38f;
            #pragma unroll
            for (int kk = 0; kk < 4; kk++) {
                int k = lane + kk * 32;
                float v = (k < 97) ? sc[qi][kk] * 0.125f + mask[qc * S_ + k]
                                   : -3.0e38f;
                sv[kk] = v;
                mx = fmaxf(mx, v);
            }
            #pragma unroll
            for (int o = 16; o > 0; o >>= 1)
                mx = fmaxf(mx, __shfl_xor_sync(0xffffffffu, mx, o));
            float sum = 0.0f;
            #pragma unroll
            for (int kk = 0; kk < 4; kk++) {
                int k = lane + kk * 32;
                float e = (k < 97) ? __expf(sv[kk] - mx) : 0.0f;
                sv[kk] = e;
                sum += e;
            }
            #pragma unroll
            for (int o = 16; o > 0; o >>= 1)
                sum += __shfl_xor_sync(0xffffffffu, sum, o);
            float inv = 1.0f / sum;
            #pragma unroll
            for (int kk = 0; kk < 4; kk++) {
                int k = lane + kk * 32;
                if (k < 97) sP[(warp * 8 + qi) * PSTRIDE + k] = sv[kk] * inv;
            }
        }
        __syncwarp();

        // ---- O = P V : lane owns d-pair (d = lane*2) ----
        {
            const int d = lane * 2;
            float2 accq[8];
            #pragma unroll
            for (int qi = 0; qi < 8; qi++) accq[qi] = make_float2(0.f, 0.f);

            #pragma unroll 2
            for (int k4 = 0; k4 < 96; k4 += 4) {
                float2 vv0 = *(const float2*)&sV[(k4 + 0) * APAD + d];
                float2 vv1 = *(const float2*)&sV[(k4 + 1) * APAD + d];
                float2 vv2 = *(const float2*)&sV[(k4 + 2) * APAD + d];
                float2 vv3 = *(const float2*)&sV[(k4 + 3) * APAD + d];
                #pragma unroll
                for (int qi = 0; qi < 8; qi++) {
                    float4 p = *(const float4*)&sP[(warp * 8 + qi) * PSTRIDE + k4];
                    accq[qi].x = fmaf(p.x, vv0.x, accq[qi].x);
                    accq[qi].y = fmaf(p.x, vv0.y, accq[qi].y);
                    accq[qi].x = fmaf(p.y, vv1.x, accq[qi].x);
                    accq[qi].y = fmaf(p.y, vv1.y, accq[qi].y);
                    accq[qi].x = fmaf(p.z, vv2.x, accq[qi].x);
                    accq[qi].y = fmaf(p.z, vv2.y, accq[qi].y);
                    accq[qi].x = fmaf(p.w, vv3.x, accq[qi].x);
                    accq[qi].y = fmaf(p.w, vv3.y, accq[qi].y);
                }
            }
            // k = 96 tail
            {
                float2 vv = *(const float2*)&sV[96 * APAD + d];
                #pragma unroll
                for (int qi = 0; qi < 8; qi++) {
                    float p = sP[(warp * 8 + qi) * PSTRIDE + 96];
                    accq[qi].x = fmaf(p, vv.x, accq[qi].x);
                    accq[qi].y = fmaf(p, vv.y, accq[qi].y);
                }
            }
            #pragma unroll
            for (int qi = 0; qi < 8; qi++) {
                int q = q0 + qi;
                if (q < 97) {
                    float2 o2 = make_float2(tf32r(accq[qi].x), tf32r(accq[qi].y));
                    *(float2*)&O[(size_t)q * srow + base + d] = o2;
                }
            }
        }
        __syncwarp();
    }
}

// ---------------------------------------------------------------------------
// Host launcher
// ---------------------------------------------------------------------------
extern "C" void kernel_launch(void* const* d_in, const int* in_sizes, int n_in,
                              void* d_out, int out_size)
{
    (void)in_sizes; (void)n_in; (void)out_size;
    const float* tensor = (const float*)d_in[0];
    const float* mask   = (const float*)d_in[1];
    const float* q_w    = (const float*)d_in[2];
    const float* q_b    = (const float*)d_in[3];
    const float* k_w    = (const float*)d_in[4];
    const float* k_b    = (const float*)d_in[5];
    const float* v_w    = (const float*)d_in[6];
    const float* v_b    = (const float*)d_in[7];
    const float* ipw    = (const float*)d_in[8];
    const float* ipb    = (const float*)d_in[9];
    const float* mow    = (const float*)d_in[10];
    const float* mob    = (const float*)d_in[11];
    const float* ow     = (const float*)d_in[12];
    const float* ob     = (const float*)d_in[13];
    float* out = (float*)d_out;

    float *b0, *b1, *b2, *b3, *b4, *b5, *tR, *wr, *ct, *st;
    cudaGetSymbolAddress((void**)&b0, g_b0);
    cudaGetSymbolAddress((void**)&b1, g_b1);
    cudaGetSymbolAddress((void**)&b2, g_b2);
    cudaGetSymbolAddress((void**)&b3, g_b3);
    cudaGetSymbolAddress((void**)&b4, g_b4);
    cudaGetSymbolAddress((void**)&b5, g_b5);
    cudaGetSymbolAddress((void**)&tR, g_t);
    cudaGetSymbolAddress((void**)&wr, g_wr);
    cudaGetSymbolAddress((void**)&ct, g_cos);
    cudaGetSymbolAddress((void**)&st, g_sin);

    cudaFuncSetAttribute(gemm_kernel, cudaFuncAttributeMaxDynamicSharedMemorySize,
                         GEMM_SMEM_BYTES);
    cudaFuncSetAttribute(attn_kernel, cudaFuncAttributeMaxDynamicSharedMemorySize,
                         ATTN_SMEM_BYTES);

    rope_tab_kernel<<<(S_ * 512 + 255) / 256, 256>>>(ct, st);

    // One-time tf32 pre-rounding of the tensor-core operands
    const int MW4 = (M_ * W_) / 4;
    const int WW4 = (1024 * 1024) / 4;
    round_tf32_kernel<<<(MW4 + 255) / 256, 256>>>((const float4*)tensor, (float4*)tR, MW4);
    round_tf32_kernel<<<(WW4 + 255) / 256, 256>>>((const float4*)q_w, (float4*)(wr + 0), WW4);
    round_tf32_kernel<<<(WW4 + 255) / 256, 256>>>((const float4*)k_w, (float4*)(wr + 1048576), WW4);
    round_tf32_kernel<<<(WW4 + 255) / 256, 256>>>((const float4*)v_w, (float4*)(wr + 2097152), WW4);
    round_tf32_kernel<<<(3 * WW4 + 255) / 256, 256>>>((const float4*)ipw, (float4*)(wr + 3145728), 3 * WW4);
    round_tf32_kernel<<<(WW4 + 255) / 256, 256>>>((const float4*)mow, (float4*)(wr + 6291456), WW4);
    round_tf32_kernel<<<(WW4 + 255) / 256, 256>>>((const float4*)ow,  (float4*)(wr + 7340032), WW4);

    dim3 gg(NDIM / BN, M_ / BM);   // (8, 194)

    // Stage 1: first projections (+RoPE on q,k); outputs feed tensor cores -> round
    gemm_kernel<<<gg, 256, GEMM_SMEM_BYTES>>>(tR, wr + 0,       q_b, b0, FLG_ROPE | FLG_ROUND, ct, st);
    gemm_kernel<<<gg, 256, GEMM_SMEM_BYTES>>>(tR, wr + 1048576, k_b, b1, FLG_ROPE | FLG_ROUND, ct, st);
    gemm_kernel<<<gg, 256, GEMM_SMEM_BYTES>>>(tR, wr + 2097152, v_b, b2, FLG_ROUND, ct, st);

    // Stage 2: in_proj split projections; outputs feed fp32 attention -> no round
    gemm_kernel<<<gg, 256, GEMM_SMEM_BYTES>>>(b0, wr + 3145728, ipb,        b3, 0, ct, st);
    gemm_kernel<<<gg, 256, GEMM_SMEM_BYTES>>>(b1, wr + 4194304, ipb + 1024, b4, 0, ct, st);
    gemm_kernel<<<gg, 256, GEMM_SMEM_BYTES>>>(b2, wr + 5242880, ipb + 2048, b5, 0, ct, st);

    // Stage 3: attention (O -> b0, output tf32-rounded in-kernel)
    attn_kernel<<<B_ * H_, 256, ATTN_SMEM_BYTES>>>(b3, b4, b5, mask, b0);

    // Stage 4: output projections
    gemm_kernel<<<gg, 256, GEMM_SMEM_BYTES>>>(b0, wr + 6291456, mob, b1, FLG_ROUND, ct, st);
    gemm_kernel<<<gg, 256, GEMM_SMEM_BYTES>>>(b1, wr + 7340032, ob,  out, 0, ct, st);
}

// round 6
// speedup vs baseline: 2.2141x; 1.9988x over previous
// Resubmission of Round-5 kernel: bench infra failed twice with no diagnostics;
// compile failures are known to surface cleanly (R3), and a full audit found no
// runtime fault. Re-benching unchanged to get a measurement.
#include <cuda_runtime.h>
#include <cuda_fp16.h>
#include <cstdint>
#include <cstddef>

// ---------------------------------------------------------------------------
// Problem constants
// ---------------------------------------------------------------------------
#define S_  97
#define B_  256
#define W_  1024
#define H_  16
#define HD_ 64
#define M_  (S_ * B_)      // 24832 = 194 * 128
#define KDIM 1024
#define NDIM 1024

// GEMM tiling: fp16 mma.sync m16n8k16 + ldmatrix, 128x128x64 tiles
#define BM 128
#define BN 128
#define BK 64                                  // halves (128 B per row)
#define ROWB 128                               // bytes per smem row
#define STAGE_BYTES ((BM + BN) * ROWB)         // 32768
#define NSTAGE 3
#define GEMM_SMEM_BYTES (NSTAGE * STAGE_BYTES + 128)
#define NITER (KDIM / BK)                      // 16

// flags
#define FLG_ROPE  1

// Attention smem
#define APAD 68
#define PSTRIDE 100
#define ATTN_SMEM_FLOATS (3 * 97 * APAD + 64 * PSTRIDE)
#define ATTN_SMEM_BYTES (ATTN_SMEM_FLOATS * 4)

// ---------------------------------------------------------------------------
// Scratch (static device globals; no allocation allowed). Used as half buffers.
// ---------------------------------------------------------------------------
__device__ float g_b0[M_ * (size_t)W_];
__device__ float g_b1[M_ * (size_t)W_];
__device__ float g_b2[M_ * (size_t)W_];
__device__ float g_b3[M_ * (size_t)W_];
__device__ float g_b4[M_ * (size_t)W_];
__device__ float g_b5[M_ * (size_t)W_];
__device__ float g_t [M_ * (size_t)W_];       // input tensor as half
__device__ float g_wr[8u * 1024u * 1024u];    // all weights as half
__device__ float g_cos[S_ * 512];
__device__ float g_sin[S_ * 512];

// ---------------------------------------------------------------------------
// Helpers
// ---------------------------------------------------------------------------
__device__ __forceinline__ uint32_t smem_u32(const void* p) {
    uint32_t a;
    asm("{ .reg .u64 t; cvta.to.shared.u64 t, %1; cvt.u32.u64 %0, t; }"
        : "=r"(a) : "l"(p));
    return a;
}

__device__ __forceinline__ void ldm4(uint32_t* r, uint32_t addr) {
    asm volatile("ldmatrix.sync.aligned.m8n8.x4.shared.b16 {%0,%1,%2,%3}, [%4];"
                 : "=r"(r[0]), "=r"(r[1]), "=r"(r[2]), "=r"(r[3]) : "r"(addr));
}

__device__ __forceinline__ void mma_f16(float* c, const uint32_t* a, const uint32_t* b) {
    asm volatile(
        "mma.sync.aligned.m16n8k16.row.col.f32.f16.f16.f32 "
        "{%0,%1,%2,%3},{%4,%5,%6,%7},{%8,%9},{%0,%1,%2,%3};"
        : "+f"(c[0]), "+f"(c[1]), "+f"(c[2]), "+f"(c[3])
        : "r"(a[0]), "r"(a[1]), "r"(a[2]), "r"(a[3]), "r"(b[0]), "r"(b[1]));
}

__device__ __forceinline__ void cp16(uint32_t s, const void* g) {
    asm volatile("cp.async.cg.shared.global [%0], [%1], 16;" :: "r"(s), "l"(g));
}

// ---------------------------------------------------------------------------
// RoPE table + f32 -> f16 convert kernels
// ---------------------------------------------------------------------------
__global__ void rope_tab_kernel(float* __restrict__ ct, float* __restrict__ st) {
    int i = blockIdx.x * 256 + threadIdx.x;
    if (i >= S_ * 512) return;
    int s = i / 512, p = i % 512;
    float inv = powf(10000.0f, -(float)p * (1.0f / 512.0f));
    float ang = (float)s * inv;
    ct[i] = cosf(ang);
    st[i] = sinf(ang);
}

__global__ void f2h_kernel(const float4* __restrict__ in, uint2* __restrict__ out, int n4) {
    int i = blockIdx.x * 256 + threadIdx.x;
    if (i >= n4) return;
    float4 v = in[i];
    __half2 h0 = __floats2half2_rn(v.x, v.y);
    __half2 h1 = __floats2half2_rn(v.z, v.w);
    uint2 u;
    u.x = *(uint32_t*)&h0;
    u.y = *(uint32_t*)&h1;
    out[i] = u;
}

// ---------------------------------------------------------------------------
// fp16 GEMM: C[M,1024] = A[M,1024] @ Wm^T + bias (+RoPE).
// A, Wm are half; acc fp32; output half (intermediates) or float (final).
// 3-stage cp.async pipeline; ldmatrix fragment loads; XOR-16B swizzled smem.
// ---------------------------------------------------------------------------
template <bool OUT_HALF>
__global__ __launch_bounds__(256, 2)
void gemm_h(const __half* __restrict__ A, const __half* __restrict__ Wm,
            const float* __restrict__ bias, void* __restrict__ Cv,
            int flags,
            const float* __restrict__ cosT, const float* __restrict__ sinT)
{
    extern __shared__ char smraw[];
    const uint32_t s0 = (smem_u32(smraw) + 127) & ~127u;

    const int tid  = threadIdx.x;
    const int lane = tid & 31;
    const int warp = tid >> 5;
    const int wr   = warp >> 2;   // 0..1 : 64 M-rows
    const int wc   = warp & 3;    // 0..3 : 32 N-cols
    const int m0   = blockIdx.y * BM;
    const int n0   = blockIdx.x * BN;

    // gmem->smem: each thread 8 chunks of 16B (4 for A, 4 for B)
    const int lrow = tid >> 3;          // 0..31 ; rows lrow + 32*i
    const int lc   = tid & 7;           // 16B chunk in row
    const int lsw  = (lc ^ (lrow & 7)) << 4;
    const __half* Abase = A  + (size_t)(m0 + lrow) * KDIM + lc * 8;
    const __half* Bbase = Wm + (size_t)(n0 + lrow) * KDIM + lc * 8;

    float acc[4][4][4];
    #pragma unroll
    for (int i = 0; i < 4; i++)
        #pragma unroll
        for (int j = 0; j < 4; j++)
            #pragma unroll
            for (int c = 0; c < 4; c++) acc[i][j][c] = 0.0f;

#define LOAD_STAGE(sg, k0)                                                        \
    do {                                                                          \
        uint32_t dA = s0 + (sg) * STAGE_BYTES;                                    \
        uint32_t dB = dA + BM * ROWB;                                             \
        _Pragma("unroll")                                                         \
        for (int i_ = 0; i_ < 4; i_++) {                                          \
            cp16(dA + (lrow + i_ * 32) * ROWB + lsw,                              \
                 Abase + (size_t)i_ * 32 * KDIM + (k0));                          \
            cp16(dB + (lrow + i_ * 32) * ROWB + lsw,                              \
                 Bbase + (size_t)i_ * 32 * KDIM + (k0));                          \
        }                                                                         \
        asm volatile("cp.async.commit_group;" ::: "memory");                      \
    } while (0)

    // ldmatrix per-lane addressing (constant across iterations):
    // A: mat = lane>>3 ; r = lane&7 ; row = wr*64 + mt*16 + r + (mat&1)*8
    //    chunk = ks*2 + (mat>>1) ; xor = r
    // B: row = wc*32 + p*16 + (mat>>1)*8 + r ; chunk = ks*2 + (mat&1) ; xor = r
    const int amat = lane >> 3, ar = lane & 7;
    const uint32_t aRowOff = (uint32_t)(wr * 64 + ar + (amat & 1) * 8) * ROWB;
    const uint32_t aChunkBase = (uint32_t)(amat >> 1);
    const uint32_t bRowOff = (uint32_t)(wc * 32 + (amat >> 1) * 8 + ar) * ROWB;
    const uint32_t bChunkBase = (uint32_t)(amat & 1);

#define COMPUTE_STAGE(sg)                                                         \
    do {                                                                          \
        const uint32_t sA = s0 + (sg) * STAGE_BYTES;                              \
        const uint32_t sB = sA + BM * ROWB;                                       \
        _Pragma("unroll")                                                         \
        for (int ks = 0; ks < 4; ks++) {                                          \
            uint32_t af[4][4], bf[4][2];                                          \
            _Pragma("unroll")                                                     \
            for (int mt = 0; mt < 4; mt++)                                        \
                ldm4(af[mt], sA + aRowOff + (uint32_t)mt * 16 * ROWB              \
                     + ((((uint32_t)ks * 2 + aChunkBase) ^ (uint32_t)ar) << 4));  \
            _Pragma("unroll")                                                     \
            for (int p = 0; p < 2; p++) {                                         \
                uint32_t tmp[4];                                                  \
                ldm4(tmp, sB + bRowOff + (uint32_t)p * 16 * ROWB                  \
                     + ((((uint32_t)ks * 2 + bChunkBase) ^ (uint32_t)ar) << 4));  \
                bf[p * 2][0] = tmp[0]; bf[p * 2][1] = tmp[1];                     \
                bf[p * 2 + 1][0] = tmp[2]; bf[p * 2 + 1][1] = tmp[3];             \
            }                                                                     \
            _Pragma("unroll")                                                     \
            for (int i_ = 0; i_ < 4; i_++)                                        \
                _Pragma("unroll")                                                 \
                for (int j_ = 0; j_ < 4; j_++)                                    \
                    mma_f16(acc[i_][j_], af[i_], bf[j_]);                         \
        }                                                                         \
    } while (0)

    LOAD_STAGE(0, 0);
    LOAD_STAGE(1, BK);

    #pragma unroll 1
    for (int t = 0; t < NITER; t++) {
        if (t + 2 < NITER) {
            asm volatile("cp.async.wait_group 1;" ::: "memory");
        } else {
            asm volatile("cp.async.wait_group 0;" ::: "memory");
        }
        __syncthreads();
        if (t + 2 < NITER)
            LOAD_STAGE((t + 2) % NSTAGE, (t + 2) * BK);
        COMPUTE_STAGE(t % NSTAGE);
    }

    // ---- epilogue: bias (+ optional RoPE); store half or float ----
    const int r  = lane >> 2;
    const int c2 = (lane & 3) * 2;
    const int doRope = flags & FLG_ROPE;
    __half* Ch = (__half*)Cv;
    float*  Cf = (float*)Cv;
    #pragma unroll
    for (int i = 0; i < 4; i++) {
        int grow0 = m0 + wr * 64 + i * 16 + r;
        #pragma unroll
        for (int j = 0; j < 4; j++) {
            int gcol = n0 + wc * 32 + j * 8 + c2;   // even
            float be = bias[gcol];
            float bo = bias[gcol + 1];
            float v0 = acc[i][j][0] + be;
            float v1 = acc[i][j][1] + bo;
            float v2 = acc[i][j][2] + be;
            float v3 = acc[i][j][3] + bo;
            if (doRope) {
                int p  = gcol >> 1;
                int s0i = grow0 >> 8;
                int s1i = (grow0 + 8) >> 8;
                float ca = cosT[s0i * 512 + p], sa = sinT[s0i * 512 + p];
                float cb = cosT[s1i * 512 + p], sb = sinT[s1i * 512 + p];
                float t0 = v0 * ca - v1 * sa;  v1 = v0 * sa + v1 * ca;  v0 = t0;
                float t2 = v2 * cb - v3 * sb;  v3 = v2 * sb + v3 * cb;  v2 = t2;
            }
            if (OUT_HALF) {
                __half2 h0 = __floats2half2_rn(v0, v1);
                __half2 h1 = __floats2half2_rn(v2, v3);
                *(__half2*)&Ch[(size_t)grow0 * NDIM + gcol]       = h0;
                *(__half2*)&Ch[(size_t)(grow0 + 8) * NDIM + gcol] = h1;
            } else {
                *(float2*)&Cf[(size_t)grow0 * NDIM + gcol]       = make_float2(v0, v1);
                *(float2*)&Cf[(size_t)(grow0 + 8) * NDIM + gcol] = make_float2(v2, v3);
            }
        }
    }
#undef LOAD_STAGE
#undef COMPUTE_STAGE
}

// ---------------------------------------------------------------------------
// Attention: one block per (b, h). half I/O, fp32 compute.
// ---------------------------------------------------------------------------
__global__ __launch_bounds__(256, 2)
void attn_kernel(const __half* __restrict__ Q, const __half* __restrict__ Kx,
                 const __half* __restrict__ V, const float* __restrict__ mask,
                 __half* __restrict__ O)
{
    extern __shared__ float sm[];
    float* sQ = sm;
    float* sK = sQ + 97 * APAD;
    float* sV = sK + 97 * APAD;
    float* sP = sV + 97 * APAD;   // [64 rows][PSTRIDE]

    const int tid  = threadIdx.x;
    const int lane = tid & 31;
    const int warp = tid >> 5;
    const int b = blockIdx.x >> 4;
    const int h = blockIdx.x & 15;
    const size_t base = (size_t)b * W_ + (size_t)h * HD_;
    const size_t srow = (size_t)B_ * W_;

    // load Q/K/V head tiles: 8 halves (16B) per iteration, convert to fp32
    for (int idx = tid; idx < 97 * 8; idx += 256) {
        int row = idx >> 3, d8 = (idx & 7) * 8;
        size_t g = (size_t)row * srow + base + d8;
        uint4 rq = *(const uint4*)(Q + g);
        uint4 rk = *(const uint4*)(Kx + g);
        uint4 rv = *(const uint4*)(V + g);
        const __half2* hq = (const __half2*)&rq;
        const __half2* hk = (const __half2*)&rk;
        const __half2* hv = (const __half2*)&rv;
        #pragma unroll
        for (int c = 0; c < 4; c++) {
            float2 f;
            f = __half22float2(hq[c]); sQ[row * APAD + d8 + c * 2] = f.x; sQ[row * APAD + d8 + c * 2 + 1] = f.y;
            f = __half22float2(hk[c]); sK[row * APAD + d8 + c * 2] = f.x; sK[row * APAD + d8 + c * 2 + 1] = f.y;
            f = __half22float2(hv[c]); sV[row * APAD + d8 + c * 2] = f.x; sV[row * APAD + d8 + c * 2 + 1] = f.y;
        }
    }
    for (int idx = tid; idx < 64 * 3; idx += 256)
        sP[(idx / 3) * PSTRIDE + 97 + (idx % 3)] = 0.0f;
    __syncthreads();

    const int kcl[4] = { lane, lane + 32, lane + 64, (lane + 96 < 97) ? lane + 96 : 0 };

    for (int pass = 0; pass < 2; pass++) {
        const int q0 = pass * 64 + warp * 8;

        float sc[8][4];
        #pragma unroll
        for (int qi = 0; qi < 8; qi++)
            #pragma unroll
            for (int kk = 0; kk < 4; kk++) sc[qi][kk] = 0.0f;

        #pragma unroll 4
        for (int d4 = 0; d4 < 64; d4 += 4) {
            float4 kv[4];
            #pragma unroll
            for (int kk = 0; kk < 4; kk++)
                kv[kk] = *(const float4*)&sK[kcl[kk] * APAD + d4];
            #pragma unroll
            for (int qi = 0; qi < 8; qi++) {
                int q = q0 + qi; if (q > 96) q = 96;
                float4 qv = *(const float4*)&sQ[q * APAD + d4];
                #pragma unroll
                for (int kk = 0; kk < 4; kk++) {
                    sc[qi][kk] = fmaf(qv.x, kv[kk].x, sc[qi][kk]);
                    sc[qi][kk] = fmaf(qv.y, kv[kk].y, sc[qi][kk]);
                    sc[qi][kk] = fmaf(qv.z, kv[kk].z, sc[qi][kk]);
                    sc[qi][kk] = fmaf(qv.w, kv[kk].w, sc[qi][kk]);
                }
            }
        }

        #pragma unroll
        for (int qi = 0; qi < 8; qi++) {
            int q = q0 + qi;
            int qc = (q > 96) ? 96 : q;
            float sv[4];
            float mx = -3.0e38f;
            #pragma unroll
            for (int kk = 0; kk < 4; kk++) {
                int k = lane + kk * 32;
                float v = (k < 97) ? sc[qi][kk] * 0.125f + mask[qc * S_ + k]
                                   : -3.0e38f;
                sv[kk] = v;
                mx = fmaxf(mx, v);
            }
            #pragma unroll
            for (int o = 16; o > 0; o >>= 1)
                mx = fmaxf(mx, __shfl_xor_sync(0xffffffffu, mx, o));
            float sum = 0.0f;
            #pragma unroll
            for (int kk = 0; kk < 4; kk++) {
                int k = lane + kk * 32;
                float e = (k < 97) ? __expf(sv[kk] - mx) : 0.0f;
                sv[kk] = e;
                sum += e;
            }
            #pragma unroll
            for (int o = 16; o > 0; o >>= 1)
                sum += __shfl_xor_sync(0xffffffffu, sum, o);
            float inv = 1.0f / sum;
            #pragma unroll
            for (int kk = 0; kk < 4; kk++) {
                int k = lane + kk * 32;
                if (k < 97) sP[(warp * 8 + qi) * PSTRIDE + k] = sv[kk] * inv;
            }
        }
        __syncwarp();

        {
            const int d = lane * 2;
            float2 accq[8];
            #pragma unroll
            for (int qi = 0; qi < 8; qi++) accq[qi] = make_float2(0.f, 0.f);

            #pragma unroll 2
            for (int k4 = 0; k4 < 96; k4 += 4) {
                float2 vv0 = *(const float2*)&sV[(k4 + 0) * APAD + d];
                float2 vv1 = *(const float2*)&sV[(k4 + 1) * APAD + d];
                float2 vv2 = *(const float2*)&sV[(k4 + 2) * APAD + d];
                float2 vv3 = *(const float2*)&sV[(k4 + 3) * APAD + d];
                #pragma unroll
                for (int qi = 0; qi < 8; qi++) {
                    float4 p = *(const float4*)&sP[(warp * 8 + qi) * PSTRIDE + k4];
                    accq[qi].x = fmaf(p.x, vv0.x, accq[qi].x);
                    accq[qi].y = fmaf(p.x, vv0.y, accq[qi].y);
                    accq[qi].x = fmaf(p.y, vv1.x, accq[qi].x);
                    accq[qi].y = fmaf(p.y, vv1.y, accq[qi].y);
                    accq[qi].x = fmaf(p.z, vv2.x, accq[qi].x);
                    accq[qi].y = fmaf(p.z, vv2.y, accq[qi].y);
                    accq[qi].x = fmaf(p.w, vv3.x, accq[qi].x);
                    accq[qi].y = fmaf(p.w, vv3.y, accq[qi].y);
                }
            }
            {
                float2 vv = *(const float2*)&sV[96 * APAD + d];
                #pragma unroll
                for (int qi = 0; qi < 8; qi++) {
                    float p = sP[(warp * 8 + qi) * PSTRIDE + 96];
                    accq[qi].x = fmaf(p, vv.x, accq[qi].x);
                    accq[qi].y = fmaf(p, vv.y, accq[qi].y);
                }
            }
            #pragma unroll
            for (int qi = 0; qi < 8; qi++) {
                int q = q0 + qi;
                if (q < 97) {
                    __half2 o2 = __floats2half2_rn(accq[qi].x, accq[qi].y);
                    *(__half2*)&O[(size_t)q * srow + base + d] = o2;
                }
            }
        }
        __syncwarp();
    }
}

// ---------------------------------------------------------------------------
// Host launcher
// ---------------------------------------------------------------------------
extern "C" void kernel_launch(void* const* d_in, const int* in_sizes, int n_in,
                              void* d_out, int out_size)
{
    (void)in_sizes; (void)n_in; (void)out_size;
    const float* tensor = (const float*)d_in[0];
    const float* mask   = (const float*)d_in[1];
    const float* q_w    = (const float*)d_in[2];
    const float* q_b    = (const float*)d_in[3];
    const float* k_w    = (const float*)d_in[4];
    const float* k_b    = (const float*)d_in[5];
    const float* v_w    = (const float*)d_in[6];
    const float* v_b    = (const float*)d_in[7];
    const float* ipw    = (const float*)d_in[8];
    const float* ipb    = (const float*)d_in[9];
    const float* mow    = (const float*)d_in[10];
    const float* mob    = (const float*)d_in[11];
    const float* ow     = (const float*)d_in[12];
    const float* ob     = (const float*)d_in[13];
    float* out = (float*)d_out;

    float *b0f, *b1f, *b2f, *b3f, *b4f, *b5f, *tf, *wf, *ct, *st;
    cudaGetSymbolAddress((void**)&b0f, g_b0);
    cudaGetSymbolAddress((void**)&b1f, g_b1);
    cudaGetSymbolAddress((void**)&b2f, g_b2);
    cudaGetSymbolAddress((void**)&b3f, g_b3);
    cudaGetSymbolAddress((void**)&b4f, g_b4);
    cudaGetSymbolAddress((void**)&b5f, g_b5);
    cudaGetSymbolAddress((void**)&tf, g_t);
    cudaGetSymbolAddress((void**)&wf, g_wr);
    cudaGetSymbolAddress((void**)&ct, g_cos);
    cudaGetSymbolAddress((void**)&st, g_sin);

    __half* hb0 = (__half*)b0f;
    __half* hb1 = (__half*)b1f;
    __half* hb2 = (__half*)b2f;
    __half* hb3 = (__half*)b3f;
    __half* hb4 = (__half*)b4f;
    __half* hb5 = (__half*)b5f;
    __half* ht  = (__half*)tf;
    __half* hw  = (__half*)wf;

    cudaFuncSetAttribute(gemm_h<true>,  cudaFuncAttributeMaxDynamicSharedMemorySize, GEMM_SMEM_BYTES);
    cudaFuncSetAttribute(gemm_h<false>, cudaFuncAttributeMaxDynamicSharedMemorySize, GEMM_SMEM_BYTES);
    cudaFuncSetAttribute(attn_kernel,   cudaFuncAttributeMaxDynamicSharedMemorySize, ATTN_SMEM_BYTES);

    rope_tab_kernel<<<(S_ * 512 + 255) / 256, 256>>>(ct, st);

    // One-time f32 -> f16 conversion of tensor + weights
    const int MW4 = (M_ * W_) / 4;
    const int WW4 = (1024 * 1024) / 4;
    f2h_kernel<<<(MW4 + 255) / 256, 256>>>((const float4*)tensor, (uint2*)ht, MW4);
    f2h_kernel<<<(WW4 + 255) / 256, 256>>>((const float4*)q_w, (uint2*)(hw + 0), WW4);
    f2h_kernel<<<(WW4 + 255) / 256, 256>>>((const float4*)k_w, (uint2*)(hw + 1048576), WW4);
    f2h_kernel<<<(WW4 + 255) / 256, 256>>>((const float4*)v_w, (uint2*)(hw + 2097152), WW4);
    f2h_kernel<<<(3 * WW4 + 255) / 256, 256>>>((const float4*)ipw, (uint2*)(hw + 3145728), 3 * WW4);
    f2h_kernel<<<(WW4 + 255) / 256, 256>>>((const float4*)mow, (uint2*)(hw + 6291456), WW4);
    f2h_kernel<<<(WW4 + 255) / 256, 256>>>((const float4*)ow,  (uint2*)(hw + 7340032), WW4);

    dim3 gg(NDIM / BN, M_ / BM);   // (8, 194)

    // Stage 1: first projections (+RoPE on q,k), half outputs
    gemm_h<true><<<gg, 256, GEMM_SMEM_BYTES>>>(ht, hw + 0,       q_b, hb0, FLG_ROPE, ct, st);
    gemm_h<true><<<gg, 256, GEMM_SMEM_BYTES>>>(ht, hw + 1048576, k_b, hb1, FLG_ROPE, ct, st);
    gemm_h<true><<<gg, 256, GEMM_SMEM_BYTES>>>(ht, hw + 2097152, v_b, hb2, 0, ct, st);

    // Stage 2: in_proj split projections, half outputs
    gemm_h<true><<<gg, 256, GEMM_SMEM_BYTES>>>(hb0, hw + 3145728, ipb,        hb3, 0, ct, st);
    gemm_h<true><<<gg, 256, GEMM_SMEM_BYTES>>>(hb1, hw + 4194304, ipb + 1024, hb4, 0, ct, st);
    gemm_h<true><<<gg, 256, GEMM_SMEM_BYTES>>>(hb2, hw + 5242880, ipb + 2048, hb5, 0, ct, st);

    // Stage 3: attention (half I/O, fp32 compute) -> hb0
    attn_kernel<<<B_ * H_, 256, ATTN_SMEM_BYTES>>>(hb3, hb4, hb5, mask, hb0);

    // Stage 4: output projections; final GEMM writes fp32 to d_out
    gemm_h<true ><<<gg, 256, GEMM_SMEM_BYTES>>>(hb0, hw + 6291456, mob, hb1, 0, ct, st);
    gemm_h<false><<<gg, 256, GEMM_SMEM_BYTES>>>(hb1, hw + 7340032, ob,  out, 0, ct, st);
}